// round 4
// baseline (speedup 1.0000x reference)
#include <cuda_runtime.h>

#define N_NODES 50000
#define N_EDGES 800000
#define DIM 128

// ---- device scratch (no allocations allowed) ----
__device__ __align__(16) float g_mean[(size_t)N_NODES * DIM];
__device__ __align__(16) float g_h[(size_t)N_NODES * DIM];
__device__ int g_cnt[N_NODES];
__device__ int g_cur[N_NODES];
__device__ int g_rowptr[N_NODES + 1];
__device__ int g_col[N_EDGES];
__device__ int g_is64;

// Read edge endpoint i of row `which` (0=src, 1=dst) under either dtype.
__device__ __forceinline__ int edge_at(const void* ei, int which, int i, int is64) {
    if (is64)
        return (int)((const long long*)ei)[(size_t)which * N_EDGES + i];
    return ((const int*)ei)[(size_t)which * N_EDGES + i];
}

// ---------------- dtype probe ----------------
// int64 node ids < 50000 => every odd 32-bit word is 0.
// int32 data: 128 random values in [0,50000) all being 0 has p ~ 0.
__global__ void k_probe(const int* __restrict__ ei32, int* __restrict__ is64) {
    int ok = 1;
    for (int j = 0; j < 128; ++j)
        if (ei32[2 * j + 1] != 0) { ok = 0; break; }
    *is64 = ok;
}

// ---------------- CSR build ----------------
__global__ void k_zero(int* __restrict__ cnt, int* __restrict__ cur) {
    int i = blockIdx.x * blockDim.x + threadIdx.x;
    if (i < N_NODES) { cnt[i] = 0; cur[i] = 0; }
}

__global__ void k_hist(const void* __restrict__ ei, int* __restrict__ cnt,
                       const int* __restrict__ is64p) {
    int i = blockIdx.x * blockDim.x + threadIdx.x;
    if (i < N_EDGES) {
        int dst = edge_at(ei, 1, i, *is64p);
        if ((unsigned)dst < N_NODES) atomicAdd(cnt + dst, 1);
    }
}

__global__ void k_scan(const int* __restrict__ cnt, int* __restrict__ rowptr) {
    const int T = 1024;
    int tid = threadIdx.x;
    const int chunk = (N_NODES + T - 1) / T;
    int beg = tid * chunk;
    int end = min(beg + chunk, N_NODES);
    int s = 0;
    for (int i = beg; i < end; ++i) s += cnt[i];
    __shared__ int sums[T];
    sums[tid] = s;
    __syncthreads();
    for (int off = 1; off < T; off <<= 1) {
        int v = (tid >= off) ? sums[tid - off] : 0;
        __syncthreads();
        sums[tid] += v;
        __syncthreads();
    }
    int run = (tid > 0) ? sums[tid - 1] : 0;
    for (int i = beg; i < end; ++i) { rowptr[i] = run; run += cnt[i]; }
    if (tid == 0) rowptr[N_NODES] = sums[T - 1];
}

__global__ void k_fill(const void* __restrict__ ei,
                       const int* __restrict__ rowptr,
                       int* __restrict__ cur,
                       int* __restrict__ col,
                       const int* __restrict__ is64p) {
    int i = blockIdx.x * blockDim.x + threadIdx.x;
    if (i < N_EDGES) {
        int is64 = *is64p;
        int src = edge_at(ei, 0, i, is64);
        int dst = edge_at(ei, 1, i, is64);
        if ((unsigned)dst < N_NODES && (unsigned)src < N_NODES) {
            int pos = rowptr[dst] + atomicAdd(cur + dst, 1);
            col[pos] = src;
        }
    }
}

// ---------------- mean aggregation: warp per node ----------------
__global__ void k_agg(const float* __restrict__ xin,
                      const int* __restrict__ rowptr,
                      const int* __restrict__ col,
                      float* __restrict__ mean) {
    int node = (blockIdx.x * blockDim.x + threadIdx.x) >> 5;
    if (node >= N_NODES) return;
    int lane = threadIdx.x & 31;
    int beg = rowptr[node], end = rowptr[node + 1];

    float4 acc = make_float4(0.f, 0.f, 0.f, 0.f);
    int e = beg;
    for (; e + 4 <= end; e += 4) {
        int s0 = col[e + 0];
        int s1 = col[e + 1];
        int s2 = col[e + 2];
        int s3 = col[e + 3];
        float4 v0 = ((const float4*)(xin + (size_t)s0 * DIM))[lane];
        float4 v1 = ((const float4*)(xin + (size_t)s1 * DIM))[lane];
        float4 v2 = ((const float4*)(xin + (size_t)s2 * DIM))[lane];
        float4 v3 = ((const float4*)(xin + (size_t)s3 * DIM))[lane];
        acc.x += v0.x + v1.x + v2.x + v3.x;
        acc.y += v0.y + v1.y + v2.y + v3.y;
        acc.z += v0.z + v1.z + v2.z + v3.z;
        acc.w += v0.w + v1.w + v2.w + v3.w;
    }
    for (; e < end; ++e) {
        int s = col[e];
        float4 v = ((const float4*)(xin + (size_t)s * DIM))[lane];
        acc.x += v.x; acc.y += v.y; acc.z += v.z; acc.w += v.w;
    }
    float inv = 1.0f / (float)max(end - beg, 1);
    acc.x *= inv; acc.y *= inv; acc.z *= inv; acc.w *= inv;
    ((float4*)(mean + (size_t)node * DIM))[lane] = acc;
}

// ---------------- fused GEMM + bias + row L2-normalize ----------------
// out[m, :DOUT] = normalize( mean[m] @ Wl + Xin[m] @ Wr + bias )
template <int DOUT>
__global__ void __launch_bounds__(256)
k_gemm(const float* __restrict__ Amean,
       const float* __restrict__ Xin,
       const float* __restrict__ Wl,
       const float* __restrict__ Wr,
       const float* __restrict__ bias,
       float* __restrict__ out) {
    constexpr int BM = 128, BK = 16;
    constexpr int NG = DOUT / 64;                 // 2 for 128, 1 for 64

    __shared__ __align__(16) float As[BM][BK];
    __shared__ float4 Bs4[BK][DOUT / 4];

    int tid = threadIdx.x;
    int tx = tid & 15;       // column group 0..15
    int ty = tid >> 4;       // row group 0..15
    int m0 = blockIdx.x * BM;

    float acc[8][NG][4];
#pragma unroll
    for (int i = 0; i < 8; ++i)
#pragma unroll
        for (int g = 0; g < NG; ++g)
#pragma unroll
            for (int j = 0; j < 4; ++j) acc[i][g][j] = 0.f;

#pragma unroll
    for (int phase = 0; phase < 2; ++phase) {
        const float* A = phase ? Xin : Amean;
        const float* W = phase ? Wr : Wl;
        for (int kk = 0; kk < DIM; kk += BK) {
            // A tile: 128x16 floats = 512 float4 loads, 2 per thread
#pragma unroll
            for (int l = 0; l < 2; ++l) {
                int idx = tid + l * 256;
                int r = idx >> 2;
                int c4 = idx & 3;
                int m = m0 + r;
                float4 v = make_float4(0.f, 0.f, 0.f, 0.f);
                if (m < N_NODES)
                    v = ((const float4*)(A + (size_t)m * DIM + kk))[c4];
                As[r][c4 * 4 + 0] = v.x;
                As[r][c4 * 4 + 1] = v.y;
                As[r][c4 * 4 + 2] = v.z;
                As[r][c4 * 4 + 3] = v.w;
            }
            // W tile: 16 x DOUT
            constexpr int WV = (BK * DOUT / 4) / 256;   // 2 or 1
#pragma unroll
            for (int l = 0; l < WV; ++l) {
                int idx = tid + l * 256;
                int r = idx / (DOUT / 4);
                int c4 = idx % (DOUT / 4);
                Bs4[r][c4] = ((const float4*)(W + (size_t)(kk + r) * DOUT))[c4];
            }
            __syncthreads();

#pragma unroll
            for (int k = 0; k < BK; ++k) {
                float a[8];
#pragma unroll
                for (int i = 0; i < 8; ++i) a[i] = As[ty * 8 + i][k];
                float4 bv[NG];
#pragma unroll
                for (int g = 0; g < NG; ++g)
                    bv[g] = Bs4[k][g * 16 + tx];
#pragma unroll
                for (int i = 0; i < 8; ++i)
#pragma unroll
                    for (int g = 0; g < NG; ++g) {
                        acc[i][g][0] += a[i] * bv[g].x;
                        acc[i][g][1] += a[i] * bv[g].y;
                        acc[i][g][2] += a[i] * bv[g].z;
                        acc[i][g][3] += a[i] * bv[g].w;
                    }
            }
            __syncthreads();
        }
    }

    // epilogue: bias + row L2 normalize + store
    float bb[NG][4];
#pragma unroll
    for (int g = 0; g < NG; ++g)
#pragma unroll
        for (int j = 0; j < 4; ++j) bb[g][j] = bias[g * 64 + tx * 4 + j];

#pragma unroll
    for (int i = 0; i < 8; ++i) {
        float ss = 0.f;
#pragma unroll
        for (int g = 0; g < NG; ++g)
#pragma unroll
            for (int j = 0; j < 4; ++j) {
                acc[i][g][j] += bb[g][j];
                ss += acc[i][g][j] * acc[i][g][j];
            }
        // reduce across the 16 tx lanes (xor bits 0..3 stay inside group)
        ss += __shfl_xor_sync(0xffffffffu, ss, 1);
        ss += __shfl_xor_sync(0xffffffffu, ss, 2);
        ss += __shfl_xor_sync(0xffffffffu, ss, 4);
        ss += __shfl_xor_sync(0xffffffffu, ss, 8);
        float sc = 1.0f / fmaxf(sqrtf(ss), 1e-12f);
        int m = m0 + ty * 8 + i;
        if (m < N_NODES) {
            float* op = out + (size_t)m * DOUT + tx * 4;
#pragma unroll
            for (int g = 0; g < NG; ++g) {
                op[g * 64 + 0] = acc[i][g][0] * sc;
                op[g * 64 + 1] = acc[i][g][1] * sc;
                op[g * 64 + 2] = acc[i][g][2] * sc;
                op[g * 64 + 3] = acc[i][g][3] * sc;
            }
        }
    }
}

extern "C" void kernel_launch(void* const* d_in, const int* in_sizes, int n_in,
                              void* d_out, int out_size) {
    const float* x    = (const float*)d_in[0];
    const void*  ei   = d_in[1];
    const float* w1_l = (const float*)d_in[2];
    const float* b1   = (const float*)d_in[3];
    const float* w1_r = (const float*)d_in[4];
    const float* w2_l = (const float*)d_in[5];
    const float* b2   = (const float*)d_in[6];
    const float* w2_r = (const float*)d_in[7];
    float* out = (float*)d_out;

    float *mean_p = nullptr, *h_p = nullptr;
    int *cnt_p = nullptr, *cur_p = nullptr, *rowptr_p = nullptr,
        *col_p = nullptr, *is64_p = nullptr;
    cudaGetSymbolAddress((void**)&mean_p, g_mean);
    cudaGetSymbolAddress((void**)&h_p, g_h);
    cudaGetSymbolAddress((void**)&cnt_p, g_cnt);
    cudaGetSymbolAddress((void**)&cur_p, g_cur);
    cudaGetSymbolAddress((void**)&rowptr_p, g_rowptr);
    cudaGetSymbolAddress((void**)&col_p, g_col);
    cudaGetSymbolAddress((void**)&is64_p, g_is64);

    // ---- dtype probe + CSR build ----
    k_probe<<<1, 1>>>((const int*)ei, is64_p);
    k_zero<<<(N_NODES + 255) / 256, 256>>>(cnt_p, cur_p);
    k_hist<<<(N_EDGES + 255) / 256, 256>>>(ei, cnt_p, is64_p);
    k_scan<<<1, 1024>>>(cnt_p, rowptr_p);
    k_fill<<<(N_EDGES + 255) / 256, 256>>>(ei, rowptr_p, cur_p, col_p, is64_p);

    // ---- layer 1: mean(x) -> g_mean; h = norm(mean@w1_l + x@w1_r + b1) ----
    k_agg<<<(N_NODES * 32 + 255) / 256, 256>>>(x, rowptr_p, col_p, mean_p);
    k_gemm<128><<<(N_NODES + 127) / 128, 256>>>(mean_p, x, w1_l, w1_r, b1, h_p);

    // ---- layer 2: mean(h) -> g_mean; out = norm(mean@w2_l + h@w2_r + b2) ----
    k_agg<<<(N_NODES * 32 + 255) / 256, 256>>>(h_p, rowptr_p, col_p, mean_p);
    k_gemm<64><<<(N_NODES + 127) / 128, 256>>>(mean_p, h_p, w2_l, w2_r, b2, out);
}